// round 16
// baseline (speedup 1.0000x reference)
#include <cuda_runtime.h>
#include <math.h>

#define BB   4
#define SS   512
#define HH   256
#define VV   32000
#define MM   (BB*SS)     // 2048
#define G3H  768

// GRU dynamic smem (max chunk len 128): sxp[128*96] + sh[2*256] + spart[96 f4]
#define SMEM_GRU ((128 * 96 + 2 * 256 + 96 * 4) * 4)

// ---------------- device scratch (no allocation anywhere) ----------------
__device__ float g_embT[(size_t)MM * HH];    // [bt][k] RNA-rounded   2 MB
__device__ float g_WihR[(size_t)G3H * HH];   // [row][k] RNA-rounded  768 KB
__device__ float g_xp[(size_t)MM * G3H];     // [bt][row]             6 MB
__device__ float g_hsR[(size_t)MM * HH];     // [bt][k] RNA-rounded   2 MB
__device__ float g_WoutR[(size_t)VV * HH];   // [n][k] RNA-rounded   33 MB
__device__ float g_hsave[BB * HH];           // h checkpoint between chunks

// ---------------- kernels fwd-decl for static init ------------------------
__global__ void gru_kernel(const float*, const float*, int, int);

// ---------------- streams/events (static init: before harness baseline) ---
namespace {
struct OverlapRes {
    cudaStream_t hi, lo;
    cudaEvent_t  ev[12];
    OverlapRes() {
        int least = 0, greatest = 0;
        cudaDeviceGetStreamPriorityRange(&least, &greatest);
        cudaStreamCreateWithPriority(&hi, cudaStreamNonBlocking, greatest);
        cudaStreamCreateWithPriority(&lo, cudaStreamNonBlocking, least);
        for (int i = 0; i < 12; i++)
            cudaEventCreateWithFlags(&ev[i], cudaEventDisableTiming);
        cudaFuncSetAttribute(gru_kernel,
                             cudaFuncAttributeMaxDynamicSharedMemorySize,
                             SMEM_GRU);
    }
};
OverlapRes g_res;
}

// RNA round fp32 -> tf32 bit pattern (round-to-nearest, ties away)
__device__ __forceinline__ float rna_tf32(float v) {
    unsigned b = __float_as_uint(v);
    b = (b + 0x1000u) & 0xFFFFE000u;
    return __uint_as_float(b);
}

// ---------------- kernel A: gather emb -> [bt][k] RNA (t-range chunk) -----
// grid 512 = 4 batches x 128 steps starting at t0
__global__ void gather_kernel(const int* __restrict__ x,
                              const float* __restrict__ emb, const int t0)
{
    const int bt  = (blockIdx.x >> 7) * SS + t0 + (blockIdx.x & 127);
    const int tid = threadIdx.x;             // 0..63
    const int tok = x[bt];
    const float4 v = *(const float4*)(emb + (size_t)tok * HH + tid * 4);
    float4 o;
    o.x = rna_tf32(v.x); o.y = rna_tf32(v.y);
    o.z = rna_tf32(v.z); o.w = rna_tf32(v.w);
    *(float4*)(g_embT + (size_t)bt * HH + tid * 4) = o;
}

// ---------------- kernel B1: RNA-round W_ih --------------------------------
__global__ void __launch_bounds__(256) roundwih_kernel(const float* __restrict__ Wih)
{
    const size_t i = (size_t)blockIdx.x * 256 + threadIdx.x;
    g_WihR[i] = rna_tf32(Wih[i]);
}

// ---------------- kernel B2: RNA-round W_out -------------------------------
__global__ void __launch_bounds__(256) roundw_kernel(const float* __restrict__ Wout)
{
    const size_t i = (size_t)blockIdx.x * 256 + threadIdx.x;
    g_WoutR[i] = rna_tf32(Wout[i]);
}

// ---------------- shared GEMM helpers --------------------------------------
#define KCH  16          // k-chunk
#define LDP  20          // padded smem row stride (floats)

__device__ __forceinline__ void cp16(unsigned smem_dst, const void* gsrc) {
    asm volatile("cp.async.cg.shared.global [%0], [%1], 16;"
                 :: "r"(smem_dst), "l"(gsrc) : "memory");
}
__device__ __forceinline__ void mma_tf32(float* d, unsigned a0, unsigned a1,
                                         unsigned a2, unsigned a3,
                                         unsigned b0, unsigned b1) {
    asm volatile(
        "mma.sync.aligned.m16n8k8.row.col.f32.tf32.tf32.f32 "
        "{%0,%1,%2,%3}, {%4,%5,%6,%7}, {%8,%9}, {%0,%1,%2,%3};"
        : "+f"(d[0]), "+f"(d[1]), "+f"(d[2]), "+f"(d[3])
        : "r"(a0), "r"(a1), "r"(a2), "r"(a3), "r"(b0), "r"(b1));
}

// ---------------- kernel B3: inproj as TF32 GEMM (t-range chunk) -----------
// xp tile = embT[b*512+toff .. +128, :] @ W_ih^T + b_ih.  grid (6, 4) x 256.
__global__ void __launch_bounds__(256, 2) inproj_mma_kernel(
    const float* __restrict__ b_ih, const int toff)
{
    __shared__ unsigned sA[2][128 * LDP];
    __shared__ unsigned sB[2][128 * LDP];

    const int m0   = blockIdx.y * SS + toff;   // 128 bt rows for one batch
    const int n0   = blockIdx.x * 128;
    const int tid  = threadIdx.x;
    const int lane = tid & 31;
    const int wid  = tid >> 5;
    const int wm   = wid & 3;
    const int wn   = wid >> 2;
    const int gid  = lane >> 2;
    const int tig  = lane & 3;

    float acc[2][8][4];
#pragma unroll
    for (int mi = 0; mi < 2; mi++)
#pragma unroll
        for (int ni = 0; ni < 8; ni++)
#pragma unroll
            for (int q = 0; q < 4; q++) acc[mi][ni][q] = 0.f;

    const int lrow = tid >> 2;
    const int lseg = (tid & 3) * 4;
    const unsigned sA0 = (unsigned)__cvta_generic_to_shared(&sA[0][0]);
    const unsigned sB0 = (unsigned)__cvta_generic_to_shared(&sB[0][0]);
    const unsigned stageBytes = 128 * LDP * 4;

#pragma unroll
    for (int p = 0; p < 2; p++) {
        const int row = p * 64 + lrow;
        cp16(sA0 + (unsigned)(row * LDP + lseg) * 4u,
             g_embT + (size_t)(m0 + row) * HH + lseg);
        cp16(sB0 + (unsigned)(row * LDP + lseg) * 4u,
             g_WihR + (size_t)(n0 + row) * HH + lseg);
    }
    asm volatile("cp.async.commit_group;" ::: "memory");

    for (int c = 0; c < HH / KCH; c++) {
        const int s = c & 1;
        if (c + 1 < HH / KCH) {
            const unsigned so = (unsigned)((c + 1) & 1) * stageBytes;
            const int k0 = (c + 1) * KCH;
#pragma unroll
            for (int p = 0; p < 2; p++) {
                const int row = p * 64 + lrow;
                cp16(sA0 + so + (unsigned)(row * LDP + lseg) * 4u,
                     g_embT + (size_t)(m0 + row) * HH + k0 + lseg);
                cp16(sB0 + so + (unsigned)(row * LDP + lseg) * 4u,
                     g_WihR + (size_t)(n0 + row) * HH + k0 + lseg);
            }
            asm volatile("cp.async.commit_group;" ::: "memory");
            asm volatile("cp.async.wait_group 1;" ::: "memory");
        } else {
            asm volatile("cp.async.wait_group 0;" ::: "memory");
        }
        __syncthreads();

#pragma unroll
        for (int ks = 0; ks < 2; ks++) {
            const int k8 = ks * 8;
            unsigned af[2][4];
#pragma unroll
            for (int mi = 0; mi < 2; mi++) {
                const int base = wm * 32 + mi * 16;
                af[mi][0] = sA[s][(base + gid) * LDP + k8 + tig];
                af[mi][1] = sA[s][(base + gid + 8) * LDP + k8 + tig];
                af[mi][2] = sA[s][(base + gid) * LDP + k8 + tig + 4];
                af[mi][3] = sA[s][(base + gid + 8) * LDP + k8 + tig + 4];
            }
#pragma unroll
            for (int ni = 0; ni < 8; ni++) {
                const int nb = wn * 64 + ni * 8;
                const unsigned b0 = sB[s][(nb + gid) * LDP + k8 + tig];
                const unsigned b1 = sB[s][(nb + gid) * LDP + k8 + tig + 4];
#pragma unroll
                for (int mi = 0; mi < 2; mi++) {
                    mma_tf32(acc[mi][ni],
                             af[mi][0], af[mi][1], af[mi][2], af[mi][3],
                             b0, b1);
                }
            }
        }
        __syncthreads();
    }

#pragma unroll
    for (int mi = 0; mi < 2; mi++) {
        const int rbase = m0 + wm * 32 + mi * 16;
#pragma unroll
        for (int half = 0; half < 2; half++) {
            const int row = rbase + gid + half * 8;
#pragma unroll
            for (int ni = 0; ni < 8; ni++) {
                const int col = n0 + wn * 64 + ni * 8 + tig * 2;
                const float v0 = acc[mi][ni][half * 2 + 0] + b_ih[col];
                const float v1 = acc[mi][ni][half * 2 + 1] + b_ih[col + 1];
                *(float2*)(g_xp + (size_t)row * G3H + col) = make_float2(v0, v1);
            }
        }
    }
}

// ---------------- kernel C: GRU recurrence chunk (len steps) ---------------
// 4 clusters (1 per batch) x 8 CTAs x 384 threads; CTA owns cols [rank*32,+32).
// t0, len even; len in {32, 64, 128}. Steps processed in pairs so the
// buffer index (cur/nxt) is compile-time -> hoisted mapa addresses.
__global__ void __launch_bounds__(384, 1) __cluster_dims__(8, 1, 1)
gru_kernel(const float* __restrict__ W_hh, const float* __restrict__ b_hh,
           const int t0, const int len)
{
    extern __shared__ float dyn[];
    float*  sxp   = dyn;                         // [len][96]: (s, g*32+c)
    float*  sh    = dyn + 128 * 96;              // [2][256]
    float4* spart = (float4*)(dyn + 128 * 96 + 512);   // [96]

    const int tid  = threadIdx.x;
    const int w    = tid >> 5;       // 0..11
    const int lane = tid & 31;
    const int g    = w >> 2;         // gate 0..2
    const int kc   = w & 3;          // k-chunk 0..3
    unsigned rank;
    asm("mov.u32 %0, %%cluster_ctarank;" : "=r"(rank));
    const int batch = blockIdx.x >> 3;
    const int col   = (int)rank * 32 + lane;

    // preload this chunk's xp slice: len steps x 3 gates x 32 cols
    {
        const unsigned sxp_addr = (unsigned)__cvta_generic_to_shared(sxp);
        const int nq = len >> 4;
        for (int q = 0; q < nq; q++) {
            const int i  = tid + q * 384;
            const int sg = i >> 3, off = i & 7;
            const int s  = sg / 3, gg = sg - s * 3;
            const float* src = g_xp
                + (size_t)(batch * SS + t0 + s) * G3H
                + gg * HH + (int)rank * 32 + off * 4;
            cp16(sxp_addr + (unsigned)(s * 96 + gg * 32 + off * 4) * 4u, src);
        }
        asm volatile("cp.async.commit_group;" ::: "memory");
    }

    // persistent W_hh slice in registers, packed as f32x2 pairs
    unsigned long long wreg[32];
    {
        const ulonglong2* wp =
            (const ulonglong2*)(W_hh + (size_t)(g * HH + col) * HH + kc * 64);
#pragma unroll
        for (int i = 0; i < 16; i++) {
            const ulonglong2 wv = wp[i];
            wreg[2 * i + 0] = wv.x;
            wreg[2 * i + 1] = wv.y;
        }
    }

    float bhr = 0.f, bhz = 0.f, bhn = 0.f;
    int gcol = 0;
    unsigned rem01[2][8];            // hoisted remote DSMEM addrs [buf][rk]
    const unsigned sh_addr = (unsigned)__cvta_generic_to_shared(sh);
    if (tid < 32) {
        gcol = (int)rank * 32 + tid;
        bhr = b_hh[0 * HH + gcol];
        bhz = b_hh[1 * HH + gcol];
        bhn = b_hh[2 * HH + gcol];
#pragma unroll
        for (int nb = 0; nb < 2; nb++) {
            const unsigned dst = sh_addr + (unsigned)(nb * HH + gcol) * 4u;
#pragma unroll
            for (int rk = 0; rk < 8; rk++)
                asm volatile("mapa.shared::cluster.u32 %0, %1, %2;"
                             : "=r"(rem01[nb][rk]) : "r"(dst), "r"((unsigned)rk));
        }
    }

    if (tid < HH)
        sh[tid] = (t0 == 0) ? 0.f : g_hsave[batch * HH + tid];
    asm volatile("cp.async.wait_group 0;" ::: "memory");
    __syncthreads();
    asm volatile("barrier.cluster.arrive.aligned;" ::: "memory");

    const int tend = t0 + len;
    for (int tt = t0 + 1; tt <= tend; tt += 2) {
#pragma unroll
        for (int half = 0; half < 2; half++) {
            const int t   = tt + half;
            const int cur = half;            // t0 even: (t-1)&1 == half
            const int nxt = 1 - half;
            const int s   = t - 1 - t0;

            asm volatile("barrier.cluster.wait.aligned;" ::: "memory");

            {
                const float* hb = sh + cur * HH + kc * 64;
                unsigned long long a0 = 0ULL, a1 = 0ULL;
#pragma unroll
                for (int i = 0; i < 64; i += 8) {
                    const ulonglong2 h0 = *(const ulonglong2*)(hb + i);
                    const ulonglong2 h1 = *(const ulonglong2*)(hb + i + 4);
                    asm("fma.rn.f32x2 %0, %1, %2, %0;"
                        : "+l"(a0) : "l"(wreg[i / 2 + 0]), "l"(h0.x));
                    asm("fma.rn.f32x2 %0, %1, %2, %0;"
                        : "+l"(a1) : "l"(wreg[i / 2 + 1]), "l"(h0.y));
                    asm("fma.rn.f32x2 %0, %1, %2, %0;"
                        : "+l"(a0) : "l"(wreg[i / 2 + 2]), "l"(h1.x));
                    asm("fma.rn.f32x2 %0, %1, %2, %0;"
                        : "+l"(a1) : "l"(wreg[i / 2 + 3]), "l"(h1.y));
                }
                const float sv = __uint_as_float((unsigned)(a0 & 0xffffffffu))
                               + __uint_as_float((unsigned)(a0 >> 32))
                               + __uint_as_float((unsigned)(a1 & 0xffffffffu))
                               + __uint_as_float((unsigned)(a1 >> 32));
                ((float*)&spart[g * 32 + lane])[kc] = sv;
            }
            __syncthreads();

            float hnew = 0.f;
            if (tid < 32) {
                const float xr = sxp[s * 96 +  0 + tid];
                const float xz = sxp[s * 96 + 32 + tid];
                const float xn = sxp[s * 96 + 64 + tid];
                const float4 p0 = spart[0 * 32 + tid];
                const float4 p1 = spart[1 * 32 + tid];
                const float4 p2 = spart[2 * 32 + tid];
                const float hr = p0.x + p0.y + p0.z + p0.w + bhr;
                const float hz = p1.x + p1.y + p1.z + p1.w + bhz;
                const float hn = p2.x + p2.y + p2.z + p2.w + bhn;
                const float r  = __fdividef(1.f, 1.f + __expf(-(xr + hr)));
                const float z  = __fdividef(1.f, 1.f + __expf(-(xz + hz)));
                const float nv = xn + r * hn;
                const float n  = 1.f - __fdividef(2.f, __expf(2.f * nv) + 1.f);
                const float ho = sh[cur * HH + gcol];
                hnew = (1.f - z) * n + z * ho;

#pragma unroll
                for (int rk = 0; rk < 8; rk++)
                    asm volatile("st.shared::cluster.f32 [%0], %1;"
                                 :: "r"(rem01[nxt][rk]), "f"(hnew) : "memory");
            }

            asm volatile("barrier.cluster.arrive.aligned;" ::: "memory");

            if (tid < 32) {
                g_hsR[(size_t)(batch * SS + t - 1) * HH + gcol] = rna_tf32(hnew);
                if (t == tend)
                    g_hsave[batch * HH + gcol] = hnew;
            }
        }
    }
    asm volatile("barrier.cluster.wait.aligned;" ::: "memory");
}

// ---------------- kernel D: output GEMM (TF32 mma, 128x128) ----------------
// MODE 0: rows = by*512 + moff + lr                (one batch, 128 steps)
// MODE 1: rows = (2*by + lr/64)*512 + moff + lr%64 (2 batches x 64 steps)
// MODE 2: rows = (lr/32)*512 + moff + lr%32        (4 batches x 32 steps)
template <int MODE>
__device__ __forceinline__ int bt_map(int by, int moff, int lr) {
    if (MODE == 0) return by * SS + moff + lr;
    if (MODE == 1) return (2 * by + (lr >> 6)) * SS + moff + (lr & 63);
    return (lr >> 5) * SS + moff + (lr & 31);
}

template <int MODE>
__global__ void __launch_bounds__(256, 2) gemm_out_kernel(
    const float* __restrict__ bout, const int* __restrict__ x,
    float* __restrict__ out, const int moff)
{
    __shared__ unsigned sA[2][128 * LDP];
    __shared__ unsigned sB[2][128 * LDP];

    const int by   = blockIdx.y;
    const int n0   = blockIdx.x * 128;
    const int tid  = threadIdx.x;
    const int lane = tid & 31;
    const int wid  = tid >> 5;
    const int wm   = wid & 3;
    const int wn   = wid >> 2;
    const int gid  = lane >> 2;
    const int tig  = lane & 3;

    float acc[2][8][4];
#pragma unroll
    for (int mi = 0; mi < 2; mi++)
#pragma unroll
        for (int ni = 0; ni < 8; ni++)
#pragma unroll
            for (int q = 0; q < 4; q++) acc[mi][ni][q] = 0.f;

    const int lrow = tid >> 2;
    const int lseg = (tid & 3) * 4;
    const unsigned sA0 = (unsigned)__cvta_generic_to_shared(&sA[0][0]);
    const unsigned sB0 = (unsigned)__cvta_generic_to_shared(&sB[0][0]);
    const unsigned stageBytes = 128 * LDP * 4;

#pragma unroll
    for (int p = 0; p < 2; p++) {
        const int lr = p * 64 + lrow;
        const int bt = bt_map<MODE>(by, moff, lr);
        cp16(sA0 + (unsigned)(lr * LDP + lseg) * 4u,
             g_hsR + (size_t)bt * HH + lseg);
        cp16(sB0 + (unsigned)(lr * LDP + lseg) * 4u,
             g_WoutR + (size_t)(n0 + lr) * HH + lseg);
    }
    asm volatile("cp.async.commit_group;" ::: "memory");

    for (int c = 0; c < HH / KCH; c++) {
        const int s = c & 1;
        if (c + 1 < HH / KCH) {
            const unsigned so = (unsigned)((c + 1) & 1) * stageBytes;
            const int k0 = (c + 1) * KCH;
#pragma unroll
            for (int p = 0; p < 2; p++) {
                const int lr = p * 64 + lrow;
                const int bt = bt_map<MODE>(by, moff, lr);
                cp16(sA0 + so + (unsigned)(lr * LDP + lseg) * 4u,
                     g_hsR + (size_t)bt * HH + k0 + lseg);
                cp16(sB0 + so + (unsigned)(lr * LDP + lseg) * 4u,
                     g_WoutR + (size_t)(n0 + lr) * HH + k0 + lseg);
            }
            asm volatile("cp.async.commit_group;" ::: "memory");
            asm volatile("cp.async.wait_group 1;" ::: "memory");
        } else {
            asm volatile("cp.async.wait_group 0;" ::: "memory");
        }
        __syncthreads();

#pragma unroll
        for (int ks = 0; ks < 2; ks++) {
            const int k8 = ks * 8;
            unsigned af[2][4];
#pragma unroll
            for (int mi = 0; mi < 2; mi++) {
                const int base = wm * 32 + mi * 16;
                af[mi][0] = sA[s][(base + gid) * LDP + k8 + tig];
                af[mi][1] = sA[s][(base + gid + 8) * LDP + k8 + tig];
                af[mi][2] = sA[s][(base + gid) * LDP + k8 + tig + 4];
                af[mi][3] = sA[s][(base + gid + 8) * LDP + k8 + tig + 4];
            }
#pragma unroll
            for (int ni = 0; ni < 8; ni++) {
                const int nb = wn * 64 + ni * 8;
                const unsigned b0 = sB[s][(nb + gid) * LDP + k8 + tig];
                const unsigned b1 = sB[s][(nb + gid) * LDP + k8 + tig + 4];
#pragma unroll
                for (int mi = 0; mi < 2; mi++) {
                    mma_tf32(acc[mi][ni],
                             af[mi][0], af[mi][1], af[mi][2], af[mi][3],
                             b0, b1);
                }
            }
        }
        __syncthreads();
    }

#pragma unroll
    for (int mi = 0; mi < 2; mi++) {
#pragma unroll
        for (int half = 0; half < 2; half++) {
            const int lr  = wm * 32 + mi * 16 + gid + half * 8;
            const int row = bt_map<MODE>(by, moff, lr);   // bt
            const int t   = row & (SS - 1);
            const bool pz = (t > 0) && (x[row - 1] == 0);
#pragma unroll
            for (int ni = 0; ni < 8; ni++) {
                const int col = n0 + wn * 64 + ni * 8 + tig * 2;
                float v0 = acc[mi][ni][half * 2 + 0] + bout[col];
                float v1 = acc[mi][ni][half * 2 + 1] + bout[col + 1];
                if (pz) {
                    if (col >= 3)     v0 = -INFINITY;
                    if (col + 1 >= 3) v1 = -INFINITY;
                }
                *(float2*)(out + (size_t)row * VV + col) = make_float2(v0, v1);
            }
        }
    }
}

// ---------------- launch ---------------------------------------------------
extern "C" void kernel_launch(void* const* d_in, const int* in_sizes, int n_in,
                              void* d_out, int out_size)
{
    const int*   x     = (const int*)  d_in[0];
    const float* emb   = (const float*)d_in[1];
    const float* W_ih  = (const float*)d_in[2];
    const float* W_hh  = (const float*)d_in[3];
    const float* b_ih  = (const float*)d_in[4];
    const float* b_hh  = (const float*)d_in[5];
    const float* W_out = (const float*)d_in[6];
    const float* b_out = (const float*)d_in[7];
    float* out = (float*)d_out;

    cudaStream_t hi = g_res.hi, lo = g_res.lo;
    cudaEvent_t* ev = g_res.ev;
    // ev[0]=fork, ev[1..6]=gru chunks 0..5, ev[7]=hi join,
    // ev[8..10]=inproj chunks 1..3, ev[11]=lo join

    cudaEventRecord(ev[0], 0);
    cudaStreamWaitEvent(hi, ev[0], 0);
    cudaStreamWaitEvent(lo, ev[0], 0);

    // hi: t<128 prologue only, then the GRU chain
    gather_kernel<<<512, 64, 0, hi>>>(x, emb, 0);
    roundwih_kernel<<<(G3H * HH) / 256, 256, 0, hi>>>(W_ih);
    inproj_mma_kernel<<<dim3(G3H / 128, BB), 256, 0, hi>>>(b_ih, 0);

    // lo: remaining prologue t-chunks (gate gru1..3), then W_out rounding
    for (int q = 1; q < 4; q++) {
        gather_kernel<<<512, 64, 0, lo>>>(x, emb, q * 128);
        inproj_mma_kernel<<<dim3(G3H / 128, BB), 256, 0, lo>>>(b_ih, q * 128);
        cudaEventRecord(ev[7 + q], lo);
    }
    roundw_kernel<<<(VV * HH) / 256, 256, 0, lo>>>(W_out);

    // GRU chunks: {128,128,128,64,32,32}
    const int t0s[6]  = {0, 128, 256, 384, 448, 480};
    const int lens[6] = {128, 128, 128, 64, 32, 32};
    for (int j = 0; j < 6; j++) {
        if (j >= 1 && j <= 3) cudaStreamWaitEvent(hi, ev[7 + j], 0);  // xp ready
        gru_kernel<<<32, 384, SMEM_GRU, hi>>>(W_hh, b_hh, t0s[j], lens[j]);
        cudaEventRecord(ev[1 + j], hi);
    }

    // GEMM chunks on lo, gated on GRU completions
    for (int j = 0; j < 3; j++) {
        cudaStreamWaitEvent(lo, ev[1 + j], 0);
        gemm_out_kernel<0><<<dim3(VV / 128, BB), 256, 0, lo>>>(b_out, x, out, j * 128);
    }
    cudaStreamWaitEvent(lo, ev[4], 0);
    gemm_out_kernel<1><<<dim3(VV / 128, BB / 2), 256, 0, lo>>>(b_out, x, out, 384);
    cudaStreamWaitEvent(lo, ev[5], 0);
    gemm_out_kernel<2><<<dim3(VV / 128, 1), 256, 0, lo>>>(b_out, x, out, 448);
    cudaStreamWaitEvent(lo, ev[6], 0);
    gemm_out_kernel<2><<<dim3(VV / 128, 1), 256, 0, lo>>>(b_out, x, out, 480);

    // join both streams back into the origin stream
    cudaEventRecord(ev[7], hi);
    cudaEventRecord(ev[11], lo);
    cudaStreamWaitEvent(0, ev[7], 0);
    cudaStreamWaitEvent(0, ev[11], 0);
}

// round 17
// speedup vs baseline: 1.1081x; 1.1081x over previous
#include <cuda_runtime.h>
#include <math.h>

#define BB   4
#define SS   512
#define HH   256
#define VV   32000
#define MM   (BB*SS)     // 2048
#define G3H  768

// GRU dynamic smem (max chunk len 128): sxp[128*96] + sh[2*256] + spart[96 f4]
#define SMEM_GRU ((128 * 96 + 2 * 256 + 96 * 4) * 4)

// ---------------- device scratch (no allocation anywhere) ----------------
__device__ float g_embT[(size_t)MM * HH];    // [bt][k] RNA-rounded   2 MB
__device__ float g_WihR[(size_t)G3H * HH];   // [row][k] RNA-rounded  768 KB
__device__ float g_xp[(size_t)MM * G3H];     // [bt][row]             6 MB
__device__ float g_hsR[(size_t)MM * HH];     // [bt][k] RNA-rounded   2 MB
__device__ float g_WoutR[(size_t)VV * HH];   // [n][k] RNA-rounded   33 MB
__device__ float g_hsave[BB * HH];           // h checkpoint between chunks

// ---------------- kernels fwd-decl for static init ------------------------
__global__ void gru_kernel(const float*, const float*, int, int);

// ---------------- streams/events (static init: before harness baseline) ---
namespace {
struct OverlapRes {
    cudaStream_t hi, lo;
    cudaEvent_t  ev[10];
    OverlapRes() {
        int least = 0, greatest = 0;
        cudaDeviceGetStreamPriorityRange(&least, &greatest);
        cudaStreamCreateWithPriority(&hi, cudaStreamNonBlocking, greatest);
        cudaStreamCreateWithPriority(&lo, cudaStreamNonBlocking, least);
        for (int i = 0; i < 10; i++)
            cudaEventCreateWithFlags(&ev[i], cudaEventDisableTiming);
        cudaFuncSetAttribute(gru_kernel,
                             cudaFuncAttributeMaxDynamicSharedMemorySize,
                             SMEM_GRU);
    }
};
OverlapRes g_res;
}

// RNA round fp32 -> tf32 bit pattern (round-to-nearest, ties away)
__device__ __forceinline__ float rna_tf32(float v) {
    unsigned b = __float_as_uint(v);
    b = (b + 0x1000u) & 0xFFFFE000u;
    return __uint_as_float(b);
}

// ---------------- kernel A: gather emb -> [bt][k], RNA-rounded ------------
__global__ void gather_kernel(const int* __restrict__ x,
                              const float* __restrict__ emb)
{
    const int bt  = blockIdx.x;
    const int tid = threadIdx.x;             // 0..63
    const int tok = x[bt];
    const float4 v = *(const float4*)(emb + (size_t)tok * HH + tid * 4);
    float4 o;
    o.x = rna_tf32(v.x); o.y = rna_tf32(v.y);
    o.z = rna_tf32(v.z); o.w = rna_tf32(v.w);
    *(float4*)(g_embT + (size_t)bt * HH + tid * 4) = o;
}

// ---------------- kernel B1: RNA-round W_ih --------------------------------
__global__ void __launch_bounds__(256) roundwih_kernel(const float* __restrict__ Wih)
{
    const size_t i = (size_t)blockIdx.x * 256 + threadIdx.x;
    g_WihR[i] = rna_tf32(Wih[i]);
}

// ---------------- kernel B2: RNA-round W_out -------------------------------
__global__ void __launch_bounds__(256) roundw_kernel(const float* __restrict__ Wout)
{
    const size_t i = (size_t)blockIdx.x * 256 + threadIdx.x;
    g_WoutR[i] = rna_tf32(Wout[i]);
}

// ---------------- shared GEMM helpers --------------------------------------
#define KCH  16          // k-chunk
#define LDP  20          // padded smem row stride (floats)

__device__ __forceinline__ void cp16(unsigned smem_dst, const void* gsrc) {
    asm volatile("cp.async.cg.shared.global [%0], [%1], 16;"
                 :: "r"(smem_dst), "l"(gsrc) : "memory");
}
__device__ __forceinline__ void mma_tf32(float* d, unsigned a0, unsigned a1,
                                         unsigned a2, unsigned a3,
                                         unsigned b0, unsigned b1) {
    asm volatile(
        "mma.sync.aligned.m16n8k8.row.col.f32.tf32.tf32.f32 "
        "{%0,%1,%2,%3}, {%4,%5,%6,%7}, {%8,%9}, {%0,%1,%2,%3};"
        : "+f"(d[0]), "+f"(d[1]), "+f"(d[2]), "+f"(d[3])
        : "r"(a0), "r"(a1), "r"(a2), "r"(a3), "r"(b0), "r"(b1));
}

// ---------------- kernel B3: inproj as TF32 GEMM ---------------------------
// xp[2048 x 768] = embT[2048 x 256] @ W_ih^T + b_ih.  grid (6, 16) x 256.
__global__ void __launch_bounds__(256, 2) inproj_mma_kernel(
    const float* __restrict__ b_ih)
{
    __shared__ unsigned sA[2][128 * LDP];
    __shared__ unsigned sB[2][128 * LDP];

    const int m0   = blockIdx.y * 128;   // bt tile
    const int n0   = blockIdx.x * 128;   // W_ih row tile (0..767)
    const int tid  = threadIdx.x;
    const int lane = tid & 31;
    const int wid  = tid >> 5;
    const int wm   = wid & 3;
    const int wn   = wid >> 2;
    const int gid  = lane >> 2;
    const int tig  = lane & 3;

    float acc[2][8][4];
#pragma unroll
    for (int mi = 0; mi < 2; mi++)
#pragma unroll
        for (int ni = 0; ni < 8; ni++)
#pragma unroll
            for (int q = 0; q < 4; q++) acc[mi][ni][q] = 0.f;

    const int lrow = tid >> 2;
    const int lseg = (tid & 3) * 4;
    const unsigned sA0 = (unsigned)__cvta_generic_to_shared(&sA[0][0]);
    const unsigned sB0 = (unsigned)__cvta_generic_to_shared(&sB[0][0]);
    const unsigned stageBytes = 128 * LDP * 4;

#pragma unroll
    for (int p = 0; p < 2; p++) {
        const int row = p * 64 + lrow;
        cp16(sA0 + (unsigned)(row * LDP + lseg) * 4u,
             g_embT + (size_t)(m0 + row) * HH + lseg);
        cp16(sB0 + (unsigned)(row * LDP + lseg) * 4u,
             g_WihR + (size_t)(n0 + row) * HH + lseg);
    }
    asm volatile("cp.async.commit_group;" ::: "memory");

    for (int c = 0; c < HH / KCH; c++) {
        const int s = c & 1;
        if (c + 1 < HH / KCH) {
            const unsigned so = (unsigned)((c + 1) & 1) * stageBytes;
            const int k0 = (c + 1) * KCH;
#pragma unroll
            for (int p = 0; p < 2; p++) {
                const int row = p * 64 + lrow;
                cp16(sA0 + so + (unsigned)(row * LDP + lseg) * 4u,
                     g_embT + (size_t)(m0 + row) * HH + k0 + lseg);
                cp16(sB0 + so + (unsigned)(row * LDP + lseg) * 4u,
                     g_WihR + (size_t)(n0 + row) * HH + k0 + lseg);
            }
            asm volatile("cp.async.commit_group;" ::: "memory");
            asm volatile("cp.async.wait_group 1;" ::: "memory");
        } else {
            asm volatile("cp.async.wait_group 0;" ::: "memory");
        }
        __syncthreads();

#pragma unroll
        for (int ks = 0; ks < 2; ks++) {
            const int k8 = ks * 8;
            unsigned af[2][4];
#pragma unroll
            for (int mi = 0; mi < 2; mi++) {
                const int base = wm * 32 + mi * 16;
                af[mi][0] = sA[s][(base + gid) * LDP + k8 + tig];
                af[mi][1] = sA[s][(base + gid + 8) * LDP + k8 + tig];
                af[mi][2] = sA[s][(base + gid) * LDP + k8 + tig + 4];
                af[mi][3] = sA[s][(base + gid + 8) * LDP + k8 + tig + 4];
            }
#pragma unroll
            for (int ni = 0; ni < 8; ni++) {
                const int nb = wn * 64 + ni * 8;
                const unsigned b0 = sB[s][(nb + gid) * LDP + k8 + tig];
                const unsigned b1 = sB[s][(nb + gid) * LDP + k8 + tig + 4];
#pragma unroll
                for (int mi = 0; mi < 2; mi++) {
                    mma_tf32(acc[mi][ni],
                             af[mi][0], af[mi][1], af[mi][2], af[mi][3],
                             b0, b1);
                }
            }
        }
        __syncthreads();
    }

    // epilogue: + b_ih, store to g_xp
#pragma unroll
    for (int mi = 0; mi < 2; mi++) {
        const int rbase = m0 + wm * 32 + mi * 16;
#pragma unroll
        for (int half = 0; half < 2; half++) {
            const int row = rbase + gid + half * 8;    // bt
#pragma unroll
            for (int ni = 0; ni < 8; ni++) {
                const int col = n0 + wn * 64 + ni * 8 + tig * 2;
                const float v0 = acc[mi][ni][half * 2 + 0] + b_ih[col];
                const float v1 = acc[mi][ni][half * 2 + 1] + b_ih[col + 1];
                *(float2*)(g_xp + (size_t)row * G3H + col) = make_float2(v0, v1);
            }
        }
    }
}

// ---------------- kernel C: GRU recurrence chunk (len steps) ---------------
// 4 clusters (1 per batch) x 8 CTAs x 384 threads; CTA owns cols [rank*32,+32).
// t0, len even; len in {64, 128}. Steps processed in compile-time pairs so
// cur/nxt are constants -> hoisted mapa addresses, no dynamic indexing.
__global__ void __launch_bounds__(384, 1) __cluster_dims__(8, 1, 1)
gru_kernel(const float* __restrict__ W_hh, const float* __restrict__ b_hh,
           const int t0, const int len)
{
    extern __shared__ float dyn[];
    float*  sxp   = dyn;                         // [len][96]: (s, g*32+c)
    float*  sh    = dyn + 128 * 96;              // [2][256]
    float4* spart = (float4*)(dyn + 128 * 96 + 512);   // [96]

    const int tid  = threadIdx.x;
    const int w    = tid >> 5;       // 0..11
    const int lane = tid & 31;
    const int g    = w >> 2;         // gate 0..2
    const int kc   = w & 3;          // k-chunk 0..3
    unsigned rank;
    asm("mov.u32 %0, %%cluster_ctarank;" : "=r"(rank));
    const int batch = blockIdx.x >> 3;
    const int col   = (int)rank * 32 + lane;

    // preload this chunk's xp slice: len steps x 3 gates x 32 cols
    {
        const unsigned sxp_addr = (unsigned)__cvta_generic_to_shared(sxp);
        const int nq = len >> 4;
        for (int q = 0; q < nq; q++) {
            const int i  = tid + q * 384;
            const int sg = i >> 3, off = i & 7;
            const int s  = sg / 3, gg = sg - s * 3;
            const float* src = g_xp
                + (size_t)(batch * SS + t0 + s) * G3H
                + gg * HH + (int)rank * 32 + off * 4;
            cp16(sxp_addr + (unsigned)(s * 96 + gg * 32 + off * 4) * 4u, src);
        }
        asm volatile("cp.async.commit_group;" ::: "memory");
    }

    // persistent W_hh slice in registers, packed as f32x2 pairs
    unsigned long long wreg[32];
    {
        const ulonglong2* wp =
            (const ulonglong2*)(W_hh + (size_t)(g * HH + col) * HH + kc * 64);
#pragma unroll
        for (int i = 0; i < 16; i++) {
            const ulonglong2 wv = wp[i];
            wreg[2 * i + 0] = wv.x;
            wreg[2 * i + 1] = wv.y;
        }
    }

    float bhr = 0.f, bhz = 0.f, bhn = 0.f;
    int gcol = 0;
    unsigned rem0[8], rem1[8];       // hoisted remote DSMEM addrs per buffer
    const unsigned sh_addr = (unsigned)__cvta_generic_to_shared(sh);
    if (tid < 32) {
        gcol = (int)rank * 32 + tid;
        bhr = b_hh[0 * HH + gcol];
        bhz = b_hh[1 * HH + gcol];
        bhn = b_hh[2 * HH + gcol];
        const unsigned d0 = sh_addr + (unsigned)gcol * 4u;
        const unsigned d1 = sh_addr + (unsigned)(HH + gcol) * 4u;
#pragma unroll
        for (int rk = 0; rk < 8; rk++) {
            asm volatile("mapa.shared::cluster.u32 %0, %1, %2;"
                         : "=r"(rem0[rk]) : "r"(d0), "r"((unsigned)rk));
            asm volatile("mapa.shared::cluster.u32 %0, %1, %2;"
                         : "=r"(rem1[rk]) : "r"(d1), "r"((unsigned)rk));
        }
    }

    if (tid < HH)
        sh[tid] = (t0 == 0) ? 0.f : g_hsave[batch * HH + tid];
    asm volatile("cp.async.wait_group 0;" ::: "memory");
    __syncthreads();
    asm volatile("barrier.cluster.arrive.aligned;" ::: "memory");

    const int tend = t0 + len;
    for (int tt = t0 + 1; tt <= tend; tt += 2) {
#pragma unroll
        for (int half = 0; half < 2; half++) {
            const int t   = tt + half;
            const int cur = half;            // t0 even: (t-1)&1 == half
            const int s   = t - 1 - t0;

            asm volatile("barrier.cluster.wait.aligned;" ::: "memory");

            {
                const float* hb = sh + cur * HH + kc * 64;
                unsigned long long a0 = 0ULL, a1 = 0ULL;
#pragma unroll
                for (int i = 0; i < 64; i += 8) {
                    const ulonglong2 h0 = *(const ulonglong2*)(hb + i);
                    const ulonglong2 h1 = *(const ulonglong2*)(hb + i + 4);
                    asm("fma.rn.f32x2 %0, %1, %2, %0;"
                        : "+l"(a0) : "l"(wreg[i / 2 + 0]), "l"(h0.x));
                    asm("fma.rn.f32x2 %0, %1, %2, %0;"
                        : "+l"(a1) : "l"(wreg[i / 2 + 1]), "l"(h0.y));
                    asm("fma.rn.f32x2 %0, %1, %2, %0;"
                        : "+l"(a0) : "l"(wreg[i / 2 + 2]), "l"(h1.x));
                    asm("fma.rn.f32x2 %0, %1, %2, %0;"
                        : "+l"(a1) : "l"(wreg[i / 2 + 3]), "l"(h1.y));
                }
                const float sv = __uint_as_float((unsigned)(a0 & 0xffffffffu))
                               + __uint_as_float((unsigned)(a0 >> 32))
                               + __uint_as_float((unsigned)(a1 & 0xffffffffu))
                               + __uint_as_float((unsigned)(a1 >> 32));
                ((float*)&spart[g * 32 + lane])[kc] = sv;
            }
            __syncthreads();

            float hnew = 0.f;
            if (tid < 32) {
                const float xr = sxp[s * 96 +  0 + tid];
                const float xz = sxp[s * 96 + 32 + tid];
                const float xn = sxp[s * 96 + 64 + tid];
                const float4 p0 = spart[0 * 32 + tid];
                const float4 p1 = spart[1 * 32 + tid];
                const float4 p2 = spart[2 * 32 + tid];
                const float hr = p0.x + p0.y + p0.z + p0.w + bhr;
                const float hz = p1.x + p1.y + p1.z + p1.w + bhz;
                const float hn = p2.x + p2.y + p2.z + p2.w + bhn;
                const float r  = __fdividef(1.f, 1.f + __expf(-(xr + hr)));
                const float z  = __fdividef(1.f, 1.f + __expf(-(xz + hz)));
                const float nv = xn + r * hn;
                const float n  = 1.f - __fdividef(2.f, __expf(2.f * nv) + 1.f);
                const float ho = sh[cur * HH + gcol];
                hnew = (1.f - z) * n + z * ho;

                if (half == 0) {      // writing buffer 1
#pragma unroll
                    for (int rk = 0; rk < 8; rk++)
                        asm volatile("st.shared::cluster.f32 [%0], %1;"
                                     :: "r"(rem1[rk]), "f"(hnew) : "memory");
                } else {              // writing buffer 0
#pragma unroll
                    for (int rk = 0; rk < 8; rk++)
                        asm volatile("st.shared::cluster.f32 [%0], %1;"
                                     :: "r"(rem0[rk]), "f"(hnew) : "memory");
                }
            }

            asm volatile("barrier.cluster.arrive.aligned;" ::: "memory");

            if (tid < 32) {
                g_hsR[(size_t)(batch * SS + t - 1) * HH + gcol] = rna_tf32(hnew);
                if (t == tend)
                    g_hsave[batch * HH + gcol] = hnew;
            }
        }
    }
    asm volatile("barrier.cluster.wait.aligned;" ::: "memory");
}

// ---------------- kernel D: output GEMM (TF32 mma, 128x128) ----------------
// MODE 0: rows = by*512 + moff + lr                (one batch, 128 steps)
// MODE 1: rows = (2*by + lr/64)*512 + moff + lr%64 (2 batches x 64 steps)
template <int MODE>
__device__ __forceinline__ int bt_map(int by, int moff, int lr) {
    if (MODE == 0) return by * SS + moff + lr;
    return (2 * by + (lr >> 6)) * SS + moff + (lr & 63);
}

template <int MODE>
__global__ void __launch_bounds__(256, 2) gemm_out_kernel(
    const float* __restrict__ bout, const int* __restrict__ x,
    float* __restrict__ out, const int moff)
{
    __shared__ unsigned sA[2][128 * LDP];
    __shared__ unsigned sB[2][128 * LDP];

    const int by   = blockIdx.y;
    const int n0   = blockIdx.x * 128;
    const int tid  = threadIdx.x;
    const int lane = tid & 31;
    const int wid  = tid >> 5;
    const int wm   = wid & 3;
    const int wn   = wid >> 2;
    const int gid  = lane >> 2;
    const int tig  = lane & 3;

    float acc[2][8][4];
#pragma unroll
    for (int mi = 0; mi < 2; mi++)
#pragma unroll
        for (int ni = 0; ni < 8; ni++)
#pragma unroll
            for (int q = 0; q < 4; q++) acc[mi][ni][q] = 0.f;

    const int lrow = tid >> 2;
    const int lseg = (tid & 3) * 4;
    const unsigned sA0 = (unsigned)__cvta_generic_to_shared(&sA[0][0]);
    const unsigned sB0 = (unsigned)__cvta_generic_to_shared(&sB[0][0]);
    const unsigned stageBytes = 128 * LDP * 4;

#pragma unroll
    for (int p = 0; p < 2; p++) {
        const int lr = p * 64 + lrow;
        const int bt = bt_map<MODE>(by, moff, lr);
        cp16(sA0 + (unsigned)(lr * LDP + lseg) * 4u,
             g_hsR + (size_t)bt * HH + lseg);
        cp16(sB0 + (unsigned)(lr * LDP + lseg) * 4u,
             g_WoutR + (size_t)(n0 + lr) * HH + lseg);
    }
    asm volatile("cp.async.commit_group;" ::: "memory");

    for (int c = 0; c < HH / KCH; c++) {
        const int s = c & 1;
        if (c + 1 < HH / KCH) {
            const unsigned so = (unsigned)((c + 1) & 1) * stageBytes;
            const int k0 = (c + 1) * KCH;
#pragma unroll
            for (int p = 0; p < 2; p++) {
                const int lr = p * 64 + lrow;
                const int bt = bt_map<MODE>(by, moff, lr);
                cp16(sA0 + so + (unsigned)(lr * LDP + lseg) * 4u,
                     g_hsR + (size_t)bt * HH + k0 + lseg);
                cp16(sB0 + so + (unsigned)(lr * LDP + lseg) * 4u,
                     g_WoutR + (size_t)(n0 + lr) * HH + k0 + lseg);
            }
            asm volatile("cp.async.commit_group;" ::: "memory");
            asm volatile("cp.async.wait_group 1;" ::: "memory");
        } else {
            asm volatile("cp.async.wait_group 0;" ::: "memory");
        }
        __syncthreads();

#pragma unroll
        for (int ks = 0; ks < 2; ks++) {
            const int k8 = ks * 8;
            unsigned af[2][4];
#pragma unroll
            for (int mi = 0; mi < 2; mi++) {
                const int base = wm * 32 + mi * 16;
                af[mi][0] = sA[s][(base + gid) * LDP + k8 + tig];
                af[mi][1] = sA[s][(base + gid + 8) * LDP + k8 + tig];
                af[mi][2] = sA[s][(base + gid) * LDP + k8 + tig + 4];
                af[mi][3] = sA[s][(base + gid + 8) * LDP + k8 + tig + 4];
            }
#pragma unroll
            for (int ni = 0; ni < 8; ni++) {
                const int nb = wn * 64 + ni * 8;
                const unsigned b0 = sB[s][(nb + gid) * LDP + k8 + tig];
                const unsigned b1 = sB[s][(nb + gid) * LDP + k8 + tig + 4];
#pragma unroll
                for (int mi = 0; mi < 2; mi++) {
                    mma_tf32(acc[mi][ni],
                             af[mi][0], af[mi][1], af[mi][2], af[mi][3],
                             b0, b1);
                }
            }
        }
        __syncthreads();
    }

    // epilogue: bias + symbolic mask + store
#pragma unroll
    for (int mi = 0; mi < 2; mi++) {
#pragma unroll
        for (int half = 0; half < 2; half++) {
            const int lr  = wm * 32 + mi * 16 + gid + half * 8;
            const int row = bt_map<MODE>(by, moff, lr);   // bt
            const int t   = row & (SS - 1);
            const bool pz = (t > 0) && (x[row - 1] == 0);
#pragma unroll
            for (int ni = 0; ni < 8; ni++) {
                const int col = n0 + wn * 64 + ni * 8 + tig * 2;
                float v0 = acc[mi][ni][half * 2 + 0] + bout[col];
                float v1 = acc[mi][ni][half * 2 + 1] + bout[col + 1];
                if (pz) {
                    if (col >= 3)     v0 = -INFINITY;
                    if (col + 1 >= 3) v1 = -INFINITY;
                }
                *(float2*)(out + (size_t)row * VV + col) = make_float2(v0, v1);
            }
        }
    }
}

// ---------------- launch ---------------------------------------------------
extern "C" void kernel_launch(void* const* d_in, const int* in_sizes, int n_in,
                              void* d_out, int out_size)
{
    const int*   x     = (const int*)  d_in[0];
    const float* emb   = (const float*)d_in[1];
    const float* W_ih  = (const float*)d_in[2];
    const float* W_hh  = (const float*)d_in[3];
    const float* b_ih  = (const float*)d_in[4];
    const float* b_hh  = (const float*)d_in[5];
    const float* W_out = (const float*)d_in[6];
    const float* b_out = (const float*)d_in[7];
    float* out = (float*)d_out;

    cudaStream_t hi = g_res.hi, lo = g_res.lo;
    cudaEvent_t* ev = g_res.ev;
    // ev[0]=fork, ev[1..5]=gru chunks 0..4, ev[6]=hi join, ev[7]=lo join

    cudaEventRecord(ev[0], 0);
    cudaStreamWaitEvent(hi, ev[0], 0);
    cudaStreamWaitEvent(lo, ev[0], 0);

    // hi: gather -> round W_ih -> inproj GEMM -> 5x GRU chunks
    gather_kernel<<<MM, 64, 0, hi>>>(x, emb);
    roundwih_kernel<<<(G3H * HH) / 256, 256, 0, hi>>>(W_ih);
    inproj_mma_kernel<<<dim3(G3H / 128, MM / 128), 256, 0, hi>>>(b_ih);

    // lo: W_out rounding (parallel with the hi prologue)
    roundw_kernel<<<(VV * HH) / 256, 256, 0, lo>>>(W_out);

    // GRU chunks: {128,128,128,64,64}
    const int t0s[5]  = {0, 128, 256, 384, 448};
    const int lens[5] = {128, 128, 128, 64, 64};
    for (int j = 0; j < 5; j++) {
        gru_kernel<<<32, 384, SMEM_GRU, hi>>>(W_hh, b_hh, t0s[j], lens[j]);
        cudaEventRecord(ev[1 + j], hi);
    }

    // GEMM chunks on lo, gated on GRU completions
    for (int j = 0; j < 3; j++) {
        cudaStreamWaitEvent(lo, ev[1 + j], 0);
        gemm_out_kernel<0><<<dim3(VV / 128, BB), 256, 0, lo>>>(b_out, x, out, j * 128);
    }
    cudaStreamWaitEvent(lo, ev[4], 0);
    gemm_out_kernel<1><<<dim3(VV / 128, BB / 2), 256, 0, lo>>>(b_out, x, out, 384);
    cudaStreamWaitEvent(lo, ev[5], 0);
    gemm_out_kernel<1><<<dim3(VV / 128, BB / 2), 256, 0, lo>>>(b_out, x, out, 448);

    // join both streams back into the origin stream
    cudaEventRecord(ev[6], hi);
    cudaEventRecord(ev[7], lo);
    cudaStreamWaitEvent(0, ev[6], 0);
    cudaStreamWaitEvent(0, ev[7], 0);
}